// round 2
// baseline (speedup 1.0000x reference)
#include <cuda_runtime.h>
#include <cstdint>

// Problem constants (from reference)
#define GB_T 1000000
#define GB_C 16
#define GB_G 500000
#define GB_K 9
// elements per batch in units of float4: G*K*(C/4)
#define GB_GK (GB_G * GB_K)            // 4,500,000
#define GB_PER_B (GB_GK * 4)           // 18,000,000 float4s per batch

__global__ __launch_bounds__(256)
void gather_groups_kernel(const float4* __restrict__ tex4,   // [B, T*4] float4
                          const int*    __restrict__ gidx,   // [G*K]
                          float4*       __restrict__ out4)   // [B, G*K*4]
{
    const int64_t tid = (int64_t)blockIdx.x * blockDim.x + threadIdx.x;
    if (tid >= GB_PER_B) return;
    const int b = blockIdx.y;

    const int gk = (int)(tid >> 2);      // which (g,k) element
    const int c4 = (int)(tid & 3);       // which 16-byte chunk of the 64-byte row

    const int idx = __ldg(&gidx[gk]);    // 4 consecutive threads broadcast-load same idx

    const int64_t src = (int64_t)b * (GB_T * 4) + (int64_t)idx * 4 + c4;
    const int64_t dst = (int64_t)b * GB_PER_B + tid;

    out4[dst] = __ldg(&tex4[src]);
}

extern "C" void kernel_launch(void* const* d_in, const int* in_sizes, int n_in,
                              void* d_out, int out_size) {
    // metadata order: mesh_ids (int32 [B]) — unused by reference math,
    //                 textures (float32 [B,T,C]), group_idx (int32 [G,K])
    const float4* tex4 = (const float4*)d_in[1];
    const int*    gidx = (const int*)d_in[2];
    float4*       out4 = (float4*)d_out;

    const int threads = 256;
    const int blocks = (GB_PER_B + threads - 1) / threads;  // 70313
    dim3 grid(blocks, 2, 1);  // grid.y = B

    gather_groups_kernel<<<grid, threads>>>(tex4, gidx, out4);
}

// round 3
// speedup vs baseline: 1.4025x; 1.4025x over previous
#include <cuda_runtime.h>
#include <cstdint>

// Problem constants (from reference)
#define GB_T 1000000
#define GB_C 16
#define GB_G 500000
#define GB_K 9
#define GB_GK (GB_G * GB_K)            // 4,500,000 (g,k) rows
#define GB_PER_B (GB_GK * 4)           // 18,000,000 float4s per batch
#define GB_UNROLL 4
#define GB_STRIDE (GB_PER_B / GB_UNROLL)  // 4,500,000 (exact: 18M % 4 == 0)

__global__ __launch_bounds__(256)
void gather_groups_kernel(const float4* __restrict__ tex4,   // [B, T*4] float4
                          const int*    __restrict__ gidx,   // [G*K]
                          float4*       __restrict__ out4)   // [B, G*K*4]
{
    const int tid = blockIdx.x * blockDim.x + threadIdx.x;
    if (tid >= GB_STRIDE) return;
    const int b = blockIdx.y;

    const int64_t tex_base = (int64_t)b * (GB_T * 4);
    const int64_t out_base = (int64_t)b * GB_PER_B;

    // Front-batch 4 independent index loads (MLP on the idx stream)
    int idx[GB_UNROLL];
#pragma unroll
    for (int u = 0; u < GB_UNROLL; u++) {
        const int e = tid + u * GB_STRIDE;          // element id, coalesced per-u
        idx[u] = __ldg(&gidx[e >> 2]);
    }

    // Front-batch 4 independent gather loads (MLP=4 hides L2/DRAM latency)
    float4 v[GB_UNROLL];
#pragma unroll
    for (int u = 0; u < GB_UNROLL; u++) {
        const int e  = tid + u * GB_STRIDE;
        const int c4 = e & 3;
        v[u] = __ldg(&tex4[tex_base + (int64_t)idx[u] * 4 + c4]);
    }

    // Streaming stores: evict-first, don't pollute L2 (output is never re-read)
#pragma unroll
    for (int u = 0; u < GB_UNROLL; u++) {
        const int e = tid + u * GB_STRIDE;
        __stcs(&out4[out_base + e], v[u]);
    }
}

extern "C" void kernel_launch(void* const* d_in, const int* in_sizes, int n_in,
                              void* d_out, int out_size) {
    // metadata order: mesh_ids (int32 [B]) — unused by reference math,
    //                 textures (float32 [B,T,C]), group_idx (int32 [G,K])
    const float4* tex4 = (const float4*)d_in[1];
    const int*    gidx = (const int*)d_in[2];
    float4*       out4 = (float4*)d_out;

    const int threads = 256;
    const int blocks = (GB_STRIDE + threads - 1) / threads;  // 17579
    dim3 grid(blocks, 2, 1);  // grid.y = B

    gather_groups_kernel<<<grid, threads>>>(tex4, gidx, out4);
}